// round 8
// baseline (speedup 1.0000x reference)
#include <cuda_runtime.h>
#include <cuda_fp16.h>
#include <math.h>

// Problem constants
#define BINC 288            // K*K*B = 9*32
#define CC   32             // output caps
#define PS   16             // P*P
#define NLOC 128            // b*oh*ow = 2*8*8
#define EPSF 1e-6f
#define LAMBDAF 1e-3f
#define LN2PI 1.8378770664093453f

typedef unsigned long long u64;

// scratch: v[n][i][c][q] stored fp16 (128*288*32*16 halves = 37.7MB, L2-resident)
__device__ __half d_v[(size_t)NLOC * BINC * CC * PS];

__device__ __forceinline__ float guard3(float x, float nanv, float pinf, float ninf) {
    if (isnan(x)) return nanv;
    if (isinf(x)) return x > 0.0f ? pinf : ninf;
    return x;
}

// ---- packed f32x2 helpers (sm_103a) ----
__device__ __forceinline__ u64 pack2(float lo, float hi) {
    u64 r; asm("mov.b64 %0, {%1,%2};" : "=l"(r) : "f"(lo), "f"(hi)); return r;
}
__device__ __forceinline__ u64 packb(float v) {
    u64 r; asm("mov.b64 %0, {%1,%1};" : "=l"(r) : "f"(v)); return r;
}
__device__ __forceinline__ void unpack2(u64 p, float& lo, float& hi) {
    asm("mov.b64 {%0,%1}, %2;" : "=f"(lo), "=f"(hi) : "l"(p));
}
__device__ __forceinline__ u64 fma2(u64 a, u64 b, u64 c) {
    u64 d; asm("fma.rn.f32x2 %0, %1, %2, %3;" : "=l"(d) : "l"(a), "l"(b), "l"(c)); return d;
}
__device__ __forceinline__ u64 mul2(u64 a, u64 b) {
    u64 d; asm("mul.rn.f32x2 %0, %1, %2;" : "=l"(d) : "l"(a), "l"(b)); return d;
}
__device__ __forceinline__ u64 add2(u64 a, u64 b) {
    u64 d; asm("add.rn.f32x2 %0, %1, %2;" : "=l"(d) : "l"(a), "l"(b)); return d;
}
// fp32 pair -> half2 word (lo in low half)
__device__ __forceinline__ unsigned f22h2(float lo, float hi) {
    unsigned r; asm("cvt.rn.f16x2.f32 %0, %1, %2;" : "=r"(r) : "f"(hi), "f"(lo)); return r;
}
// half2 word -> packed f32x2
__device__ __forceinline__ u64 h22f2(unsigned h) {
    float flo, fhi;
    asm("{.reg .b16 l, hh; mov.b32 {l, hh}, %2; cvt.f32.f16 %0, l; cvt.f32.f16 %1, hh;}"
        : "=f"(flo), "=f"(fhi) : "r"(h));
    return pack2(flo, fhi);
}
__device__ __forceinline__ u64 pack2u(unsigned lo, unsigned hi) {
    u64 r; asm("mov.b64 %0, {%1,%2};" : "=l"(r) : "r"(lo), "r"(hi)); return r;
}

// ---- integer hardware warp reductions (sm_80+) used for fp32 softmax ----
__device__ __forceinline__ float warp_max_f32(float x) {
    int i = __float_as_int(x);
    i = (i < 0) ? (int)(0x80000000u - (unsigned)i) : i;   // monotone map
    int m; asm("redux.sync.max.s32 %0, %1, 0xffffffff;" : "=r"(m) : "r"(i));
    m = (m < 0) ? (int)(0x80000000u - (unsigned)m) : m;   // inverse (involutive)
    return __int_as_float(m);
}
// sum of e in [0,1] with at least one lane == 1.0 ; 2^26 fixed point
__device__ __forceinline__ float warp_sum_e(float e) {
    unsigned q; asm("cvt.rni.u32.f32 %0, %1;" : "=r"(q) : "f"(e * 67108864.0f));
    unsigned s; asm("redux.sync.add.u32 %0, %1, 0xffffffff;" : "=r"(s) : "r"(q));
    return (float)s * (1.0f / 67108864.0f);
}

// ---------------------------------------------------------------------------
// Kernel 1: v[n,i,c,q] = sum_p p_in[n,i,p] * w0[i,c,p,q]   (stored fp16)
// one block per i (288 blocks), 512 threads. Packed f32x2 FMA.
// Replicates the reference's reshape scramble:
//   L = i*16+p ; kk2=L/512 ; ch2=L%512 ; F=kk2*544+ch2 ; ch=F/9 ; kk=F%9
// ---------------------------------------------------------------------------
__global__ __launch_bounds__(512) void k_compute_v(const float* __restrict__ x,
                                                   const float* __restrict__ w) {
    const int i = blockIdx.x;
    const int t = threadIdx.x;
    __shared__ float p_s[NLOC * PS];      // 8 KB
    __shared__ float w_s[CC * PS * PS];   // 32 KB

    // load w0[i] : 8192 floats = 2048 float4
    {
        const float4* src = (const float4*)(w + (size_t)i * (CC * PS * PS));
        float4* dst = (float4*)w_s;
#pragma unroll
        for (int k = 0; k < 4; k++) dst[t + k * 512] = src[t + k * 512];
    }

    // gather p_in for all 128 locations at this i (scrambled mapping)
    for (int e = t; e < NLOC * PS; e += 512) {
        int n = e >> 4;
        int p = e & 15;
        int L = (i << 4) + p;
        int kk2 = L >> 9;
        int ch2 = L & 511;
        int F = kk2 * 544 + ch2;
        int ch = F / 9;
        int kk = F - ch * 9;
        int kh = kk / 3;
        int kw = kk - kh * 3;
        int b  = n >> 6;
        int y  = (n >> 3) & 7;
        int xx = n & 7;
        int row = 2 * y + kh - 1;
        int col = 2 * xx + kw - 1;
        float val = 0.0f;
        if ((unsigned)row < 16u && (unsigned)col < 16u)
            val = x[((b * 16 + row) * 16 + col) * 544 + ch];
        p_s[e] = val;
    }
    __syncthreads();

    // mapping: t -> (qg in [0,4), c in [0,32), ng in [0,4))
    const int qg = t & 3;
    const int c  = (t >> 2) & 31;
    const int ng = t >> 7;

    // pre-pack weights: wrp[2p] = (w.x,w.y), wrp[2p+1] = (w.z,w.w)
    u64 wrp[32];
#pragma unroll
    for (int p = 0; p < 16; p++) {
        float4 w4 = ((const float4*)w_s)[c * 64 + p * 4 + qg];
        wrp[2 * p]     = pack2(w4.x, w4.y);
        wrp[2 * p + 1] = pack2(w4.z, w4.w);
    }

    u64* vout = (u64*)d_v;   // 4 halves per u64
    for (int nn = 0; nn < 32; nn++) {
        int n = ng * 32 + nn;
        const float4* pr = (const float4*)(p_s + n * 16);
        u64 accA = 0ull, accB = 0ull;
#pragma unroll
        for (int k = 0; k < 4; k++) {
            float4 pv = pr[k];
            u64 b0 = packb(pv.x), b1 = packb(pv.y), b2 = packb(pv.z), b3 = packb(pv.w);
            int pb = 8 * k;
            accA = fma2(b0, wrp[pb + 0], accA); accB = fma2(b0, wrp[pb + 1], accB);
            accA = fma2(b1, wrp[pb + 2], accA); accB = fma2(b1, wrp[pb + 3], accB);
            accA = fma2(b2, wrp[pb + 4], accA); accB = fma2(b2, wrp[pb + 5], accB);
            accA = fma2(b3, wrp[pb + 6], accA); accB = fma2(b3, wrp[pb + 7], accB);
        }
        float a0, a1, b0f, b1f;
        unpack2(accA, a0, a1);
        unpack2(accB, b0f, b1f);
        unsigned h0 = f22h2(a0, a1);
        unsigned h1 = f22h2(b0f, b1f);
        vout[(((size_t)n * BINC + i) * CC + c) * 4 + qg] = pack2u(h0, h1);
    }
}

// ---------------------------------------------------------------------------
// Kernel 2: EM routing, fused E+M passes. One CTA per location n, 512 threads.
// 3 coalesced passes over fp16 v (M0, E1+M1, E2+M2). Packed f32x2 math,
// hardware integer redux for softmax. Single-i rounds with one-round register
// prefetch: round r+1's loads issue before round r's compute, hiding L2 latency.
// Per-warp i order (w, w+16, ...) identical to previous version -> bitwise-same sums.
// ---------------------------------------------------------------------------
#define LSTR 17
#define ROWW (32 * LSTR)   // 544 words per warp row

__global__ __launch_bounds__(512, 1) void k_routing(const float* __restrict__ x,
                                                    const float* __restrict__ beta_u,
                                                    const float* __restrict__ beta_a,
                                                    float* __restrict__ out,
                                                    int out_size) {
    const int n    = blockIdx.x;
    const int t    = threadIdx.x;
    const int lane = t & 31;   // = c during accumulation
    const int warp = t >> 5;   // 16 warps

    __shared__ float buf[16 * ROWW];  // 34 KB, reused: mu partials, then s2 partials
    __shared__ float prs[16 * 32];    // r_sum partials
    __shared__ float af_s[BINC];      // a/(a+eps)
    __shared__ float nh_cq[CC * PS];  // [c][q]  -0.5/sigma
    __shared__ float B_cq[CC * PS];   // [c][q]  -2*nh*mu
    __shared__ float aout_s[CC];
    __shared__ float CcA_s[CC];       // Cc + sum_q nh*mu^2
    __shared__ float bu_s[CC];
    __shared__ float ba_s[CC];
    __shared__ float rsum_s[CC];
    __shared__ float inv_s[CC];
    __shared__ float s0_s[CC];

    if (t < 32) { bu_s[t] = beta_u[t]; ba_s[t] = beta_a[t]; }

    // gather a_in (scrambled): i -> kk2=i/32, ch2=512+i%32
    for (int i = t; i < BINC; i += 512) {
        int kk2 = i >> 5;
        int ch2 = 512 + (i & 31);
        int F = kk2 * 544 + ch2;
        int ch = F / 9;
        int kk = F - ch * 9;
        int kh = kk / 3;
        int kw = kk - kh * 3;
        int b  = n >> 6;
        int y  = (n >> 3) & 7;
        int xx = n & 7;
        int row = 2 * y + kh - 1;
        int col = 2 * xx + kw - 1;
        float val = 0.0f;
        if ((unsigned)row < 16u && (unsigned)col < 16u)
            val = x[((b * 16 + row) * 16 + col) * 544 + ch];
        af_s[i] = val / (val + EPSF);   // sum_c of softmax r == 1 -> sum_c rr == a
    }
    __syncthreads();

    const __half* vbase = d_v + (size_t)n * (BINC * CC * PS);
    const int c_m = t >> 4;   // stats mapping
    const int q_m = t & 15;

    float final_mu = 0.0f;

    for (int pass = 0; pass < 3; pass++) {
        u64 mu2[8], s22[8];
#pragma unroll
        for (int j = 0; j < 8; j++) { mu2[j] = 0ull; s22[j] = 0ull; }
        float rsp = 0.0f;

        u64 nh2[8], B2[8];
        float Cc_r = 0.0f;
        if (pass) {
            const u64* nhp = (const u64*)(nh_cq + lane * 16);
            const u64* Bp  = (const u64*)(B_cq + lane * 16);
#pragma unroll
            for (int j = 0; j < 8; j++) { nh2[j] = nhp[j]; B2[j] = Bp[j]; }
            Cc_r = CcA_s[lane];
        }

        // 18 single-i rounds, one-round register prefetch
        const uint4* pld = (const uint4*)(vbase + warp * 512 + lane * 16);
        uint4 ra0 = pld[0], ra1 = pld[1];
#pragma unroll 1
        for (int rnd = 0; rnd < 18; rnd++) {
            int i = rnd * 16 + warp;
            uint4 nx0, nx1;
            if (rnd < 17) {
                const uint4* pn = (const uint4*)(vbase + (i + 16) * 512 + lane * 16);
                nx0 = pn[0]; nx1 = pn[1];
            }
            u64 vp[8];
            vp[0] = h22f2(ra0.x); vp[1] = h22f2(ra0.y);
            vp[2] = h22f2(ra0.z); vp[3] = h22f2(ra0.w);
            vp[4] = h22f2(ra1.x); vp[5] = h22f2(ra1.y);
            vp[6] = h22f2(ra1.z); vp[7] = h22f2(ra1.w);

            float wgt;
            if (pass == 0) {
                wgt = af_s[i] * (1.0f / 32.0f);
            } else {
                // ln_ap = CcA + sum_q (nh*v + B)*v
                u64 acc2 = 0ull;
#pragma unroll
                for (int j = 0; j < 8; j++) {
                    u64 ta = fma2(nh2[j], vp[j], B2[j]);
                    acc2 = fma2(ta, vp[j], acc2);
                }
                float alo, ahi;
                unpack2(acc2, alo, ahi);
                float acc = Cc_r + alo + ahi;
                if (isnan(acc)) acc = 0.0f;
                else if (isinf(acc)) acc = acc > 0.0f ? 50.0f : -50.0f;

                // hardware (integer) warp reductions: softmax over c (32 lanes)
                float m = warp_max_f32(acc);
                float e = __expf(acc - m);
                float s = warp_sum_e(e);
                float rv = __fdividef(e, s);
                if (isnan(rv)) rv = 1.0f / 32.0f;
                else if (isinf(rv)) rv = rv > 0.0f ? 1.0f : 0.0f;
                wgt = rv * af_s[i];
            }
            rsp += wgt;
            u64 w2 = packb(wgt);
#pragma unroll
            for (int j = 0; j < 8; j++) {
                u64 p = mul2(w2, vp[j]);
                mu2[j] = add2(mu2[j], p);
                s22[j] = fma2(p, vp[j], s22[j]);
            }
            ra0 = nx0; ra1 = nx1;
        }

        // ---- cross-warp reduce: mu partials (stride-17 slots, conflict-free) ----
        {
            float* pm = buf + warp * ROWW + lane * LSTR;
#pragma unroll
            for (int j = 0; j < 8; j++) {
                float lo, hi; unpack2(mu2[j], lo, hi);
                pm[2 * j] = lo; pm[2 * j + 1] = hi;
            }
            prs[warp * 32 + lane] = rsp;
        }
        __syncthreads();

        if (t < 32) {
            float s = 0.0f;
#pragma unroll
            for (int w2 = 0; w2 < 16; w2++) s += prs[w2 * 32 + t];
            rsum_s[t] = s;
            float inv = 1.0f / (s + EPSF);
            inv_s[t] = inv;
            s0_s[t] = s * inv;
        }
        float N1 = 0.0f;
        {
            const float* rb = buf + c_m * LSTR + q_m;
#pragma unroll
            for (int w2 = 0; w2 < 16; w2++) N1 += rb[w2 * ROWW];
        }
        __syncthreads();

        // ---- cross-warp reduce: s2 partials (reuse buf) ----
        {
            float* p2 = buf + warp * ROWW + lane * LSTR;
#pragma unroll
            for (int j = 0; j < 8; j++) {
                float lo, hi; unpack2(s22[j], lo, hi);
                p2[2 * j] = lo; p2[2 * j + 1] = hi;
            }
        }
        __syncthreads();

        float N2 = 0.0f;
        {
            const float* rb = buf + c_m * LSTR + q_m;
#pragma unroll
            for (int w2 = 0; w2 < 16; w2++) N2 += rb[w2 * ROWW];
        }

        // ---- stats: thread t = (c_m, q_m) ----
        float inv = inv_s[c_m];
        float mu  = N1 * inv;
        float s2v = N2 * inv;
        float S0  = s0_s[c_m];
        float sig = s2v - mu * mu * (2.0f - S0) + EPSF;
        sig = fmaxf(sig, 1e-4f);

        float cost = (bu_s[c_m] + 0.5f * __logf(sig)) * rsum_s[c_m];

        float mu_g  = guard3(mu, 0.0f, 1e4f, -1e4f);
        float sig_g = guard3(sig, 1e-4f, 1e4f, 1e-4f);
        sig_g = fmaxf(sig_g, 1e-4f);
        float logsq_e = 0.5f * __logf(sig_g);
        float nh = -0.5f / sig_g;
        float av = nh * mu_g * mu_g;

        float csum = cost, lsum = logsq_e, asum = av;
#pragma unroll
        for (int o = 8; o; o >>= 1) {
            csum += __shfl_xor_sync(0xffffffffu, csum, o, 16);
            lsum += __shfl_xor_sync(0xffffffffu, lsum, o, 16);
            asum += __shfl_xor_sync(0xffffffffu, asum, o, 16);
        }
        if (q_m == 0) {
            float zz = LAMBDAF * (ba_s[c_m] - csum);
            float ao = 1.0f / (1.0f + expf(-zz));
            if (isnan(ao)) ao = 0.5f;
            else ao = fminf(fmaxf(ao, 1e-4f), 1.0f - 1e-4f);
            aout_s[c_m] = ao;
            CcA_s[c_m] = -lsum - 8.0f * LN2PI + logf(ao + EPSF) + asum;
        }
        nh_cq[c_m * 16 + q_m] = nh;
        B_cq[c_m * 16 + q_m]  = -2.0f * nh * mu_g;
        final_mu = mu_g;
        __syncthreads();
    }

    // ---- output writes ----
    float pval = final_mu;   // thread t -> (c,q), index c*16+q == t
    if (out_size >= 139264) {
        out[n * 512 + t] = pval;
        if (t < 32) out[65536 + n * 32 + t] = aout_s[t];
        out[69632 + n * 544 + t] = pval;
        if (t < 32) out[69632 + n * 544 + 512 + t] = aout_s[t];
    } else if (out_size == 69632) {
        out[n * 544 + t] = pval;
        if (t < 32) out[n * 544 + 512 + t] = aout_s[t];
    } else if (out_size == 65536) {
        out[n * 512 + t] = pval;
    } else if (out_size == 4096) {
        if (t < 32) out[n * 32 + t] = aout_s[t];
    } else {
        int idx = n * 512 + t;
        if (idx < out_size) out[idx] = pval;
    }
}

// ---------------------------------------------------------------------------
extern "C" void kernel_launch(void* const* d_in, const int* in_sizes, int n_in,
                              void* d_out, int out_size) {
    const float* x  = (const float*)d_in[0];   // (2,16,16,544)
    const float* w  = (const float*)d_in[1];   // (1,288,32,16,16)
    const float* bu = (const float*)d_in[2];   // (32,)
    const float* ba = (const float*)d_in[3];   // (32,)

    k_compute_v<<<BINC, 512>>>(x, w);
    k_routing<<<NLOC, 512>>>(x, bu, ba, (float*)d_out, out_size);
}

// round 9
// speedup vs baseline: 1.0861x; 1.0861x over previous
#include <cuda_runtime.h>
#include <cuda_fp16.h>
#include <math.h>

// Problem constants
#define BINC 288            // K*K*B = 9*32
#define CC   32             // output caps
#define PS   16             // P*P
#define NLOC 128            // b*oh*ow = 2*8*8
#define EPSF 1e-6f
#define LAMBDAF 1e-3f
#define LN2PI 1.8378770664093453f

typedef unsigned long long u64;

// scratch: v[n][i][c][q] stored fp16 (128*288*32*16 halves = 37.7MB, L2-resident)
__device__ __half d_v[(size_t)NLOC * BINC * CC * PS];

__device__ __forceinline__ float guard3(float x, float nanv, float pinf, float ninf) {
    if (isnan(x)) return nanv;
    if (isinf(x)) return x > 0.0f ? pinf : ninf;
    return x;
}

// ---- packed f32x2 helpers (sm_103a) ----
__device__ __forceinline__ u64 pack2(float lo, float hi) {
    u64 r; asm("mov.b64 %0, {%1,%2};" : "=l"(r) : "f"(lo), "f"(hi)); return r;
}
__device__ __forceinline__ u64 packb(float v) {
    u64 r; asm("mov.b64 %0, {%1,%1};" : "=l"(r) : "f"(v)); return r;
}
__device__ __forceinline__ void unpack2(u64 p, float& lo, float& hi) {
    asm("mov.b64 {%0,%1}, %2;" : "=f"(lo), "=f"(hi) : "l"(p));
}
__device__ __forceinline__ u64 fma2(u64 a, u64 b, u64 c) {
    u64 d; asm("fma.rn.f32x2 %0, %1, %2, %3;" : "=l"(d) : "l"(a), "l"(b), "l"(c)); return d;
}
__device__ __forceinline__ u64 mul2(u64 a, u64 b) {
    u64 d; asm("mul.rn.f32x2 %0, %1, %2;" : "=l"(d) : "l"(a), "l"(b)); return d;
}
__device__ __forceinline__ u64 add2(u64 a, u64 b) {
    u64 d; asm("add.rn.f32x2 %0, %1, %2;" : "=l"(d) : "l"(a), "l"(b)); return d;
}
// fp32 pair -> half2 word (lo in low half)
__device__ __forceinline__ unsigned f22h2(float lo, float hi) {
    unsigned r; asm("cvt.rn.f16x2.f32 %0, %1, %2;" : "=r"(r) : "f"(hi), "f"(lo)); return r;
}
// half2 word -> packed f32x2
__device__ __forceinline__ u64 h22f2(unsigned h) {
    float flo, fhi;
    asm("{.reg .b16 l, hh; mov.b32 {l, hh}, %2; cvt.f32.f16 %0, l; cvt.f32.f16 %1, hh;}"
        : "=f"(flo), "=f"(fhi) : "r"(h));
    return pack2(flo, fhi);
}
__device__ __forceinline__ u64 pack2u(unsigned lo, unsigned hi) {
    u64 r; asm("mov.b64 %0, {%1,%2};" : "=l"(r) : "r"(lo), "r"(hi)); return r;
}

// ---- integer hardware warp reductions (sm_80+) used for fp32 softmax ----
__device__ __forceinline__ float warp_max_f32(float x) {
    int i = __float_as_int(x);
    i = (i < 0) ? (int)(0x80000000u - (unsigned)i) : i;   // monotone map
    int m; asm("redux.sync.max.s32 %0, %1, 0xffffffff;" : "=r"(m) : "r"(i));
    m = (m < 0) ? (int)(0x80000000u - (unsigned)m) : m;   // inverse (involutive)
    return __int_as_float(m);
}
// sum of e in [0,1] with at least one lane == 1.0 ; 2^26 fixed point
__device__ __forceinline__ float warp_sum_e(float e) {
    unsigned q; asm("cvt.rni.u32.f32 %0, %1;" : "=r"(q) : "f"(e * 67108864.0f));
    unsigned s; asm("redux.sync.add.u32 %0, %1, 0xffffffff;" : "=r"(s) : "r"(q));
    return (float)s * (1.0f / 67108864.0f);
}

// ---------------------------------------------------------------------------
// Kernel 1: v[n,i,c,q] = sum_p p_in[n,i,p] * w0[i,c,p,q]   (stored fp16)
// TWO i's per block (grid 144 = one full wave on 148 SMs), 512 threads.
// Per-i math identical to the 288-block version (bitwise same results).
// Replicates the reference's reshape scramble:
//   L = i*16+p ; kk2=L/512 ; ch2=L%512 ; F=kk2*544+ch2 ; ch=F/9 ; kk=F%9
// ---------------------------------------------------------------------------
__global__ __launch_bounds__(512) void k_compute_v(const float* __restrict__ x,
                                                   const float* __restrict__ w) {
    const int t = threadIdx.x;
    __shared__ float p_s[NLOC * PS];      // 8 KB
    __shared__ float w_s[CC * PS * PS];   // 32 KB

    // mapping: t -> (qg in [0,4), c in [0,32), ng in [0,4))
    const int qg = t & 3;
    const int c  = (t >> 2) & 31;
    const int ng = t >> 7;

    u64* vout = (u64*)d_v;   // 4 halves per u64

#pragma unroll 1
    for (int ii = 0; ii < 2; ii++) {
        const int i = blockIdx.x * 2 + ii;

        // load w0[i] : 8192 floats = 2048 float4
        {
            const float4* src = (const float4*)(w + (size_t)i * (CC * PS * PS));
            float4* dst = (float4*)w_s;
#pragma unroll
            for (int k = 0; k < 4; k++) dst[t + k * 512] = src[t + k * 512];
        }

        // gather p_in for all 128 locations at this i (scrambled mapping)
        for (int e = t; e < NLOC * PS; e += 512) {
            int n = e >> 4;
            int p = e & 15;
            int L = (i << 4) + p;
            int kk2 = L >> 9;
            int ch2 = L & 511;
            int F = kk2 * 544 + ch2;
            int ch = F / 9;
            int kk = F - ch * 9;
            int kh = kk / 3;
            int kw = kk - kh * 3;
            int b  = n >> 6;
            int y  = (n >> 3) & 7;
            int xx = n & 7;
            int row = 2 * y + kh - 1;
            int col = 2 * xx + kw - 1;
            float val = 0.0f;
            if ((unsigned)row < 16u && (unsigned)col < 16u)
                val = x[((b * 16 + row) * 16 + col) * 544 + ch];
            p_s[e] = val;
        }
        __syncthreads();

        // pre-pack weights: wrp[2p] = (w.x,w.y), wrp[2p+1] = (w.z,w.w)
        u64 wrp[32];
#pragma unroll
        for (int p = 0; p < 16; p++) {
            float4 w4 = ((const float4*)w_s)[c * 64 + p * 4 + qg];
            wrp[2 * p]     = pack2(w4.x, w4.y);
            wrp[2 * p + 1] = pack2(w4.z, w4.w);
        }

        for (int nn = 0; nn < 32; nn++) {
            int n = ng * 32 + nn;
            const float4* pr = (const float4*)(p_s + n * 16);
            u64 accA = 0ull, accB = 0ull;
#pragma unroll
            for (int k = 0; k < 4; k++) {
                float4 pv = pr[k];
                u64 b0 = packb(pv.x), b1 = packb(pv.y), b2 = packb(pv.z), b3 = packb(pv.w);
                int pb = 8 * k;
                accA = fma2(b0, wrp[pb + 0], accA); accB = fma2(b0, wrp[pb + 1], accB);
                accA = fma2(b1, wrp[pb + 2], accA); accB = fma2(b1, wrp[pb + 3], accB);
                accA = fma2(b2, wrp[pb + 4], accA); accB = fma2(b2, wrp[pb + 5], accB);
                accA = fma2(b3, wrp[pb + 6], accA); accB = fma2(b3, wrp[pb + 7], accB);
            }
            float a0, a1, b0f, b1f;
            unpack2(accA, a0, a1);
            unpack2(accB, b0f, b1f);
            unsigned h0 = f22h2(a0, a1);
            unsigned h1 = f22h2(b0f, b1f);
            vout[(((size_t)n * BINC + i) * CC + c) * 4 + qg] = pack2u(h0, h1);
        }
        __syncthreads();   // protect w_s/p_s before next i overwrites
    }
}

// ---------------------------------------------------------------------------
// Kernel 2: EM routing, fused E+M passes. One CTA per location n, 512 threads.
// 3 coalesced passes over fp16 v (M0, E1+M1, E2+M2). Packed f32x2 math,
// hardware integer redux for softmax reductions, two i's per round for ILP.
// (identical to the 47.6us round-7 version)
// ---------------------------------------------------------------------------
#define LSTR 17
#define ROWW (32 * LSTR)   // 544 words per warp row

__global__ __launch_bounds__(512, 1) void k_routing(const float* __restrict__ x,
                                                    const float* __restrict__ beta_u,
                                                    const float* __restrict__ beta_a,
                                                    float* __restrict__ out,
                                                    int out_size) {
    const int n    = blockIdx.x;
    const int t    = threadIdx.x;
    const int lane = t & 31;   // = c during accumulation
    const int warp = t >> 5;   // 16 warps

    __shared__ float buf[16 * ROWW];  // 34 KB, reused: mu partials, then s2 partials
    __shared__ float prs[16 * 32];    // r_sum partials
    __shared__ float af_s[BINC];      // a/(a+eps)
    __shared__ float nh_cq[CC * PS];  // [c][q]  -0.5/sigma
    __shared__ float B_cq[CC * PS];   // [c][q]  -2*nh*mu
    __shared__ float aout_s[CC];
    __shared__ float CcA_s[CC];       // Cc + sum_q nh*mu^2
    __shared__ float bu_s[CC];
    __shared__ float ba_s[CC];
    __shared__ float rsum_s[CC];
    __shared__ float inv_s[CC];
    __shared__ float s0_s[CC];

    if (t < 32) { bu_s[t] = beta_u[t]; ba_s[t] = beta_a[t]; }

    // gather a_in (scrambled): i -> kk2=i/32, ch2=512+i%32
    for (int i = t; i < BINC; i += 512) {
        int kk2 = i >> 5;
        int ch2 = 512 + (i & 31);
        int F = kk2 * 544 + ch2;
        int ch = F / 9;
        int kk = F - ch * 9;
        int kh = kk / 3;
        int kw = kk - kh * 3;
        int b  = n >> 6;
        int y  = (n >> 3) & 7;
        int xx = n & 7;
        int row = 2 * y + kh - 1;
        int col = 2 * xx + kw - 1;
        float val = 0.0f;
        if ((unsigned)row < 16u && (unsigned)col < 16u)
            val = x[((b * 16 + row) * 16 + col) * 544 + ch];
        af_s[i] = val / (val + EPSF);   // sum_c of softmax r == 1 -> sum_c rr == a
    }
    __syncthreads();

    const __half* vbase = d_v + (size_t)n * (BINC * CC * PS);
    const int c_m = t >> 4;   // stats mapping
    const int q_m = t & 15;

    float final_mu = 0.0f;

    for (int pass = 0; pass < 3; pass++) {
        u64 mu2[8], s22[8];
#pragma unroll
        for (int j = 0; j < 8; j++) { mu2[j] = 0ull; s22[j] = 0ull; }
        float rsp = 0.0f;

        u64 nh2[8], B2[8];
        float Cc_r = 0.0f;
        if (pass) {
            const u64* nhp = (const u64*)(nh_cq + lane * 16);
            const u64* Bp  = (const u64*)(B_cq + lane * 16);
#pragma unroll
            for (int j = 0; j < 8; j++) { nh2[j] = nhp[j]; B2[j] = Bp[j]; }
            Cc_r = CcA_s[lane];
        }

        // two i's per round: i0 = 32*jb + warp, i1 = i0 + 16
#pragma unroll 1
        for (int jb = 0; jb < 9; jb++) {
            int i0 = jb * 32 + warp;
            int i1 = i0 + 16;
            const uint4* vrA = (const uint4*)(vbase + i0 * 512 + lane * 16);
            const uint4* vrB = (const uint4*)(vbase + i1 * 512 + lane * 16);
            uint4 a0 = vrA[0], a1 = vrA[1];
            uint4 b0 = vrB[0], b1 = vrB[1];
            u64 vpA[8], vpB[8];
            vpA[0] = h22f2(a0.x); vpA[1] = h22f2(a0.y);
            vpA[2] = h22f2(a0.z); vpA[3] = h22f2(a0.w);
            vpA[4] = h22f2(a1.x); vpA[5] = h22f2(a1.y);
            vpA[6] = h22f2(a1.z); vpA[7] = h22f2(a1.w);
            vpB[0] = h22f2(b0.x); vpB[1] = h22f2(b0.y);
            vpB[2] = h22f2(b0.z); vpB[3] = h22f2(b0.w);
            vpB[4] = h22f2(b1.x); vpB[5] = h22f2(b1.y);
            vpB[6] = h22f2(b1.z); vpB[7] = h22f2(b1.w);

            float wgtA, wgtB;
            if (pass == 0) {
                wgtA = af_s[i0] * (1.0f / 32.0f);
                wgtB = af_s[i1] * (1.0f / 32.0f);
            } else {
                // ln_ap = CcA + sum_q (nh*v + B)*v   for both i's
                u64 accA2 = 0ull, accB2 = 0ull;
#pragma unroll
                for (int j = 0; j < 8; j++) {
                    u64 ta = fma2(nh2[j], vpA[j], B2[j]);
                    u64 tb = fma2(nh2[j], vpB[j], B2[j]);
                    accA2 = fma2(ta, vpA[j], accA2);
                    accB2 = fma2(tb, vpB[j], accB2);
                }
                float alo, ahi, blo, bhi;
                unpack2(accA2, alo, ahi);
                unpack2(accB2, blo, bhi);
                float accA = Cc_r + alo + ahi;
                float accB = Cc_r + blo + bhi;
                if (isnan(accA)) accA = 0.0f;
                else if (isinf(accA)) accA = accA > 0.0f ? 50.0f : -50.0f;
                if (isnan(accB)) accB = 0.0f;
                else if (isinf(accB)) accB = accB > 0.0f ? 50.0f : -50.0f;

                // hardware (integer) warp reductions: softmax over c (32 lanes)
                float mA = warp_max_f32(accA);
                float mB = warp_max_f32(accB);
                float eA = __expf(accA - mA);
                float eB = __expf(accB - mB);
                float sA = warp_sum_e(eA);
                float sB = warp_sum_e(eB);
                float rvA = __fdividef(eA, sA);
                float rvB = __fdividef(eB, sB);
                if (isnan(rvA)) rvA = 1.0f / 32.0f;
                else if (isinf(rvA)) rvA = rvA > 0.0f ? 1.0f : 0.0f;
                if (isnan(rvB)) rvB = 1.0f / 32.0f;
                else if (isinf(rvB)) rvB = rvB > 0.0f ? 1.0f : 0.0f;
                wgtA = rvA * af_s[i0];
                wgtB = rvB * af_s[i1];
            }
            rsp += wgtA + wgtB;
            u64 wA = packb(wgtA), wB = packb(wgtB);
#pragma unroll
            for (int j = 0; j < 8; j++) {
                u64 pA = mul2(wA, vpA[j]);
                u64 pB = mul2(wB, vpB[j]);
                mu2[j] = add2(mu2[j], pA);
                s22[j] = fma2(pA, vpA[j], s22[j]);
                mu2[j] = add2(mu2[j], pB);
                s22[j] = fma2(pB, vpB[j], s22[j]);
            }
        }

        // ---- cross-warp reduce: mu partials (stride-17 slots, conflict-free) ----
        {
            float* pm = buf + warp * ROWW + lane * LSTR;
#pragma unroll
            for (int j = 0; j < 8; j++) {
                float lo, hi; unpack2(mu2[j], lo, hi);
                pm[2 * j] = lo; pm[2 * j + 1] = hi;
            }
            prs[warp * 32 + lane] = rsp;
        }
        __syncthreads();

        if (t < 32) {
            float s = 0.0f;
#pragma unroll
            for (int w2 = 0; w2 < 16; w2++) s += prs[w2 * 32 + t];
            rsum_s[t] = s;
            float inv = 1.0f / (s + EPSF);
            inv_s[t] = inv;
            s0_s[t] = s * inv;
        }
        float N1 = 0.0f;
        {
            const float* rb = buf + c_m * LSTR + q_m;
#pragma unroll
            for (int w2 = 0; w2 < 16; w2++) N1 += rb[w2 * ROWW];
        }
        __syncthreads();

        // ---- cross-warp reduce: s2 partials (reuse buf) ----
        {
            float* p2 = buf + warp * ROWW + lane * LSTR;
#pragma unroll
            for (int j = 0; j < 8; j++) {
                float lo, hi; unpack2(s22[j], lo, hi);
                p2[2 * j] = lo; p2[2 * j + 1] = hi;
            }
        }
        __syncthreads();

        float N2 = 0.0f;
        {
            const float* rb = buf + c_m * LSTR + q_m;
#pragma unroll
            for (int w2 = 0; w2 < 16; w2++) N2 += rb[w2 * ROWW];
        }

        // ---- stats: thread t = (c_m, q_m) ----
        float inv = inv_s[c_m];
        float mu  = N1 * inv;
        float s2v = N2 * inv;
        float S0  = s0_s[c_m];
        float sig = s2v - mu * mu * (2.0f - S0) + EPSF;
        sig = fmaxf(sig, 1e-4f);

        float cost = (bu_s[c_m] + 0.5f * __logf(sig)) * rsum_s[c_m];

        float mu_g  = guard3(mu, 0.0f, 1e4f, -1e4f);
        float sig_g = guard3(sig, 1e-4f, 1e4f, 1e-4f);
        sig_g = fmaxf(sig_g, 1e-4f);
        float logsq_e = 0.5f * __logf(sig_g);
        float nh = -0.5f / sig_g;
        float av = nh * mu_g * mu_g;

        float csum = cost, lsum = logsq_e, asum = av;
#pragma unroll
        for (int o = 8; o; o >>= 1) {
            csum += __shfl_xor_sync(0xffffffffu, csum, o, 16);
            lsum += __shfl_xor_sync(0xffffffffu, lsum, o, 16);
            asum += __shfl_xor_sync(0xffffffffu, asum, o, 16);
        }
        if (q_m == 0) {
            float zz = LAMBDAF * (ba_s[c_m] - csum);
            float ao = 1.0f / (1.0f + expf(-zz));
            if (isnan(ao)) ao = 0.5f;
            else ao = fminf(fmaxf(ao, 1e-4f), 1.0f - 1e-4f);
            aout_s[c_m] = ao;
            CcA_s[c_m] = -lsum - 8.0f * LN2PI + logf(ao + EPSF) + asum;
        }
        nh_cq[c_m * 16 + q_m] = nh;
        B_cq[c_m * 16 + q_m]  = -2.0f * nh * mu_g;
        final_mu = mu_g;
        __syncthreads();
    }

    // ---- output writes ----
    float pval = final_mu;   // thread t -> (c,q), index c*16+q == t
    if (out_size >= 139264) {
        out[n * 512 + t] = pval;
        if (t < 32) out[65536 + n * 32 + t] = aout_s[t];
        out[69632 + n * 544 + t] = pval;
        if (t < 32) out[69632 + n * 544 + 512 + t] = aout_s[t];
    } else if (out_size == 69632) {
        out[n * 544 + t] = pval;
        if (t < 32) out[n * 544 + 512 + t] = aout_s[t];
    } else if (out_size == 65536) {
        out[n * 512 + t] = pval;
    } else if (out_size == 4096) {
        if (t < 32) out[n * 32 + t] = aout_s[t];
    } else {
        int idx = n * 512 + t;
        if (idx < out_size) out[idx] = pval;
    }
}

// ---------------------------------------------------------------------------
extern "C" void kernel_launch(void* const* d_in, const int* in_sizes, int n_in,
                              void* d_out, int out_size) {
    const float* x  = (const float*)d_in[0];   // (2,16,16,544)
    const float* w  = (const float*)d_in[1];   // (1,288,32,16,16)
    const float* bu = (const float*)d_in[2];   // (32,)
    const float* ba = (const float*)d_in[3];   // (32,)

    k_compute_v<<<BINC / 2, 512>>>(x, w);
    k_routing<<<NLOC, 512>>>(x, bu, ba, (float*)d_out, out_size);
}